// round 13
// baseline (speedup 1.0000x reference)
#include <cuda_runtime.h>

#define B_    32768
#define W_    5
#define L_    20
#define CE_   32
#define OC_   30
#define WE_   50
#define HID_  100
#define TAGS_ 36
#define TPOS  18

#define SPB   64
#define PSTR  68
#define GP    152         // g_pool row stride (floats), 16B-aligned

typedef unsigned long long ull;

__device__ float g_Pk[3 * 100 * 32];     // [k][c][oc]
__device__ float g_A[5 * 100 * 104];     // [w][v][j]
__device__ float g_C[150 * 104];         // [k][j]
__device__ float g_pool[B_ * GP];        // [sample][150 pooled feats], 19.9 MB (L2)

// ---------------- packed fp32x2 helpers ----------------
__device__ __forceinline__ ull ffma2(ull a, ull b, ull c) {
    ull d;
    asm("fma.rn.f32x2 %0, %1, %2, %3;" : "=l"(d) : "l"(a), "l"(b), "l"(c));
    return d;
}
__device__ __forceinline__ ull add2(ull a, ull b) {
    ull d;
    asm("add.rn.f32x2 %0, %1, %2;" : "=l"(d) : "l"(a), "l"(b));
    return d;
}
__device__ __forceinline__ ull pack2(float lo, float hi) {
    ull r;
    asm("mov.b64 %0, {%1, %2};"
        : "=l"(r) : "r"(__float_as_uint(lo)), "r"(__float_as_uint(hi)));
    return r;
}
__device__ __forceinline__ void unpack2(ull v, float& lo, float& hi) {
    unsigned int a, b;
    asm("mov.b64 {%0, %1}, %2;" : "=r"(a), "=r"(b) : "l"(v));
    lo = __uint_as_float(a);
    hi = __uint_as_float(b);
}

// ---------------- Kernel 0: build P, A, C tables ----------------
__global__ void prep_kernel(const float* __restrict__ cemb,
                            const float* __restrict__ convw,
                            const float* __restrict__ wemb,
                            const float* __restrict__ fc1w)
{
    const int idx = blockIdx.x * 256 + threadIdx.x;
    if (idx < 9600) {
        const int k  = idx / 3200;
        const int r  = idx - k * 3200;
        const int c  = r >> 5;
        const int oc = r & 31;
        float s = 0.f;
        if (oc < OC_) {
            const float* wr = convw + oc * (CE_ * 3) + k;
            const float* er = cemb + c * CE_;
            float p0 = 0.f, p1 = 0.f, p2 = 0.f, p3 = 0.f;
#pragma unroll
            for (int ce = 0; ce < CE_; ce += 4) {
                p0 = fmaf(wr[(ce + 0) * 3], er[ce + 0], p0);
                p1 = fmaf(wr[(ce + 1) * 3], er[ce + 1], p1);
                p2 = fmaf(wr[(ce + 2) * 3], er[ce + 2], p2);
                p3 = fmaf(wr[(ce + 3) * 3], er[ce + 3], p3);
            }
            s = (p0 + p1) + (p2 + p3);
        }
        g_Pk[idx] = s;
    } else if (idx < 59600) {
        const int e = idx - 9600;
        const int w = e / 10000;
        const int r = e - w * 10000;
        const int v = r / 100;
        const int j = r - v * 100;
        const float* wr = fc1w + j * 400 + w * 80;
        const float* er = wemb + v * WE_;
        float p0 = 0.f, p1 = 0.f, p2 = 0.f, p3 = 0.f;
#pragma unroll
        for (int d = 0; d < 48; d += 4) {
            p0 = fmaf(wr[d + 0], er[d + 0], p0);
            p1 = fmaf(wr[d + 1], er[d + 1], p1);
            p2 = fmaf(wr[d + 2], er[d + 2], p2);
            p3 = fmaf(wr[d + 3], er[d + 3], p3);
        }
        p0 = fmaf(wr[48], er[48], p0);
        p1 = fmaf(wr[49], er[49], p1);
        g_A[(w * 100 + v) * 104 + j] = (p0 + p1) + (p2 + p3);
    } else {
        const int e = idx - 59600;
        if (e >= 150 * HID_) return;
        const int j  = e / 150;
        const int kk = e - j * 150;
        const int w  = kk / OC_;
        const int oc = kk - w * OC_;
        g_C[kk * 104 + j] = fc1w[j * 400 + w * 80 + 50 + oc];
    }
}

// ---------------- Kernel 1: conv only (high occupancy) ----------------
// 256 threads, 8 warps x 2 words x 16 iters = 256 words/block, 640 blocks.
__global__ __launch_bounds__(256, 4)
void conv_kernel(const int* __restrict__ inp, const float* __restrict__ convb)
{
    __shared__ __align__(16) float P_sh[9600];
    __shared__ int idbuf[8 * 96];
    __shared__ float cb2[32];

    const int tid  = threadIdx.x;
    const int warp = tid >> 5;
    const int lane = tid & 31;

    for (int i = tid; i < 9600; i += 256) P_sh[i] = g_Pk[i];
    if (tid < 32) cb2[tid] = (tid < OC_) ? convb[tid] : 0.f;
    __syncthreads();

    const int half = lane >> 4;
    const int ocp  = lane & 15;
    const char* Pb = (const char*)P_sh + ocp * 8;
    int* buf0 = idbuf + warp * 96;
    int* buf1 = buf0 + 48;

    {
        const int* rp = inp + (blockIdx.x * 256 + warp * 2) * 21;
        int a = 0, b = 0;
        if (lane < 21) { a = rp[lane]; b = rp[21 + lane]; }
        if (lane < 21) { buf0[lane] = a * 128; buf0[21 + lane] = b * 128; }
    }
    __syncwarp();

    for (int it = 0; it < 16; ++it) {
        const int wl = it * 16 + warp * 2;
        int* cur = (it & 1) ? buf1 : buf0;
        int* nxt = (it & 1) ? buf0 : buf1;

        int na = 0, nb = 0;
        if (it < 15) {
            const int* rp = inp + (blockIdx.x * 256 + wl + 16) * 21;
            if (lane < 21) { na = rp[lane]; nb = rp[21 + lane]; }
        }

        const int* myid = cur + half * 21 + 1;
        int ca = myid[0], cb_ = myid[1];
        ull acc[TPOS];
#pragma unroll
        for (int t = 0; t < TPOS; ++t) {
            const int cc = myid[t + 2];
            const ull x0 = *(const ull*)(Pb + ca);
            const ull x1 = *(const ull*)(Pb + 12800 + cb_);
            const ull x2 = *(const ull*)(Pb + 25600 + cc);
            acc[t] = add2(add2(x0, x1), x2);
            ca = cb_; cb_ = cc;
        }

        float m0, m1;
        unpack2(acc[0], m0, m1);
#pragma unroll
        for (int t = 1; t < TPOS; ++t) {
            float x, y;
            unpack2(acc[t], x, y);
            m0 = fmaxf(m0, x);
            m1 = fmaxf(m1, y);
        }
        if (ocp < 15) {
            const int gw = blockIdx.x * 256 + wl + half;
            const int s  = gw / W_;
            const int wi = gw - s * W_;
            *(ull*)&g_pool[s * GP + wi * OC_ + 2 * ocp] =
                pack2(m0 + cb2[2 * ocp], m1 + cb2[2 * ocp + 1]);
        }

        if (it < 15 && lane < 21) { nxt[lane] = na * 128; nxt[21 + lane] = nb * 128; }
        __syncwarp();
    }
}

// ---------------- Kernel 2: fc1 + tanh + out ----------------
// 256 threads, 64 samples/block, 512 blocks.
__global__ __launch_bounds__(256, 3)
void fc_kernel(const int* __restrict__ inp,
               const float* __restrict__ fc1w, const float* __restrict__ fc1b,
               const float* __restrict__ outw, const float* __restrict__ outb,
               const float* __restrict__ wemb,
               float* __restrict__ out)
{
    extern __shared__ __align__(16) float smem[];
    float* poolT  = smem;                    // [150][68] = 10200 ; later hT[100][68]
    float* owd    = smem + 10200;            // [100][72] = 7200
    int*   wid_sh = (int*)(smem + 17400);    // 320
    float* b_sh   = smem + 17720;            // 104
    float* ob_sh  = smem + 17824;            // 36

    const int tid  = threadIdx.x;
    const int warp = tid >> 5;
    const int lane = tid & 31;
    const int s0   = blockIdx.x * SPB;

    // stage word ids, pooled (transpose), owd, biases
    for (int i = tid; i < SPB * W_; i += 256)
        wid_sh[i] = inp[(s0 * W_ + i) * 21];
    for (int i = tid; i < SPB * 150; i += 256) {
        const int s = i / 150;
        const int k = i - s * 150;
        poolT[k * PSTR + s] = g_pool[(s0 + s) * GP + k];
    }
    for (int i = tid; i < TAGS_ * HID_; i += 256) {
        const int t = i / HID_;
        const int j = i - t * HID_;
        const float w = outw[i];
        owd[j * 72 + 2 * t]     = w;
        owd[j * 72 + 2 * t + 1] = w;
    }
    if (tid < 104) b_sh[tid] = (tid < HID_) ? fc1b[tid] : 0.f;
    if (tid < TAGS_) ob_sh[tid] = outb[tid];
    __syncthreads();

    // Phase 2: init accumulators from A table
    const int jg = tid >> 3;
    const int sg = tid & 7;
    const int j0 = jg * 4;
    const int sb = sg * 8;
    const bool active = (tid < 200);

    ull acc[16];
    if (active) {
        const float4 bias4 = *(const float4*)&b_sh[j0];
#pragma unroll
        for (int p = 0; p < 4; ++p) {
            const int sA = sb + 2 * p;
            float4 a4 = bias4, b4 = bias4;
#pragma unroll
            for (int w = 0; w < W_; ++w) {
                const int vA = wid_sh[sA * W_ + w];
                const int vB = wid_sh[(sA + 1) * W_ + w];
                if (vA < 100) {
                    const float4 t = *(const float4*)&g_A[(w * 100 + vA) * 104 + j0];
                    a4.x += t.x; a4.y += t.y; a4.z += t.z; a4.w += t.w;
                } else {
                    const float* er = wemb + vA * WE_;
                    for (int d = 0; d < WE_; ++d) {
                        const float e = er[d];
                        a4.x += fc1w[(j0+0)*400 + w*80 + d] * e;
                        a4.y += fc1w[(j0+1)*400 + w*80 + d] * e;
                        a4.z += fc1w[(j0+2)*400 + w*80 + d] * e;
                        a4.w += fc1w[(j0+3)*400 + w*80 + d] * e;
                    }
                }
                if (vB < 100) {
                    const float4 t = *(const float4*)&g_A[(w * 100 + vB) * 104 + j0];
                    b4.x += t.x; b4.y += t.y; b4.z += t.z; b4.w += t.w;
                } else {
                    const float* er = wemb + vB * WE_;
                    for (int d = 0; d < WE_; ++d) {
                        const float e = er[d];
                        b4.x += fc1w[(j0+0)*400 + w*80 + d] * e;
                        b4.y += fc1w[(j0+1)*400 + w*80 + d] * e;
                        b4.z += fc1w[(j0+2)*400 + w*80 + d] * e;
                        b4.w += fc1w[(j0+3)*400 + w*80 + d] * e;
                    }
                }
            }
            acc[p]      = pack2(a4.x, b4.x);
            acc[4 + p]  = pack2(a4.y, b4.y);
            acc[8 + p]  = pack2(a4.z, b4.z);
            acc[12 + p] = pack2(a4.w, b4.w);
        }
    }

    // Phase 3: GEMM, C via broadcast LDG.128 (L2-hot), zero barriers
    if (active) {
        const float* cbase = g_C + j0;
#pragma unroll 5
        for (int kk = 0; kk < 150; ++kk) {
            const float4 wq = *(const float4*)(cbase + kk * 104);
            const float* fr = &poolT[kk * PSTR + sb];
            const ulonglong2 fA = *(const ulonglong2*)(fr);
            const ulonglong2 fB = *(const ulonglong2*)(fr + 4);
            const ull w0 = pack2(wq.x, wq.x);
            const ull w1 = pack2(wq.y, wq.y);
            const ull w2 = pack2(wq.z, wq.z);
            const ull w3 = pack2(wq.w, wq.w);
            acc[0]  = ffma2(fA.x, w0, acc[0]);
            acc[4]  = ffma2(fA.x, w1, acc[4]);
            acc[8]  = ffma2(fA.x, w2, acc[8]);
            acc[12] = ffma2(fA.x, w3, acc[12]);
            acc[1]  = ffma2(fA.y, w0, acc[1]);
            acc[5]  = ffma2(fA.y, w1, acc[5]);
            acc[9]  = ffma2(fA.y, w2, acc[9]);
            acc[13] = ffma2(fA.y, w3, acc[13]);
            acc[2]  = ffma2(fB.x, w0, acc[2]);
            acc[6]  = ffma2(fB.x, w1, acc[6]);
            acc[10] = ffma2(fB.x, w2, acc[10]);
            acc[14] = ffma2(fB.x, w3, acc[14]);
            acc[3]  = ffma2(fB.y, w0, acc[3]);
            acc[7]  = ffma2(fB.y, w1, acc[7]);
            acc[11] = ffma2(fB.y, w2, acc[11]);
            acc[15] = ffma2(fB.y, w3, acc[15]);
        }
    }
    __syncthreads();

    // tanh -> hT[j][s] (overlays poolT)
    float* hT = poolT;
    if (active) {
#pragma unroll
        for (int jj = 0; jj < 4; ++jj)
#pragma unroll
            for (int p = 0; p < 4; ++p) {
                float a, c;
                unpack2(acc[jj * 4 + p], a, c);
                *(ull*)&hT[(j0 + jj) * PSTR + sb + 2 * p] = pack2(tanhf(a), tanhf(c));
            }
    }
    __syncthreads();

    // Phase 4: out layer; warp covers tag-quads t0 = warp*4 (+32 for warp 0)
    for (int t0 = warp * 4; t0 < TAGS_; t0 += 32) {
        ull a4[4];
#pragma unroll
        for (int p = 0; p < 4; ++p) a4[p] = 0ull;
#pragma unroll 4
        for (int j = 0; j < HID_; ++j) {
            const ull h = *(const ull*)&hT[j * PSTR + 2 * lane];
            const float* wr = &owd[j * 72 + 2 * t0];
            const ulonglong2 w01 = *(const ulonglong2*)(wr);
            const ulonglong2 w23 = *(const ulonglong2*)(wr + 4);
            a4[0] = ffma2(h, w01.x, a4[0]);
            a4[1] = ffma2(h, w01.y, a4[1]);
            a4[2] = ffma2(h, w23.x, a4[2]);
            a4[3] = ffma2(h, w23.y, a4[3]);
        }
        float r0[4], r1[4];
#pragma unroll
        for (int tt = 0; tt < 4; ++tt) {
            float a, c;
            unpack2(a4[tt], a, c);
            const float bo = ob_sh[t0 + tt];
            r0[tt] = a + bo;
            r1[tt] = c + bo;
        }
        float* op0 = out + (s0 + 2 * lane) * TAGS_ + t0;
        *(float4*)op0           = make_float4(r0[0], r0[1], r0[2], r0[3]);
        *(float4*)(op0 + TAGS_) = make_float4(r1[0], r1[1], r1[2], r1[3]);
    }
}

// ---------------- launch ----------------
extern "C" void kernel_launch(void* const* d_in, const int* in_sizes, int n_in,
                              void* d_out, int out_size)
{
    const int*   inp   = (const int*)  d_in[0];
    const float* wemb  = (const float*)d_in[1];
    const float* cemb  = (const float*)d_in[2];
    const float* convw = (const float*)d_in[3];
    const float* convb = (const float*)d_in[4];
    const float* fc1w  = (const float*)d_in[5];
    const float* fc1b  = (const float*)d_in[6];
    const float* outw  = (const float*)d_in[7];
    const float* outb  = (const float*)d_in[8];
    float* out = (float*)d_out;

    const int fc_smem = 17860 * 4 + 128;   // ~71.6 KB
    cudaFuncSetAttribute(fc_kernel,
                         cudaFuncAttributeMaxDynamicSharedMemorySize, fc_smem);

    prep_kernel<<<(9600 + 50000 + 15000 + 255) / 256, 256>>>(cemb, convw, wemb, fc1w);
    conv_kernel<<<(B_ * W_) / 256, 256>>>(inp, convb);
    fc_kernel<<<B_ / SPB, 256, fc_smem>>>(inp, fc1w, fc1b, outw, outb, wemb, out);
}

// round 14
// speedup vs baseline: 1.1245x; 1.1245x over previous
#include <cuda_runtime.h>

#define B_    32768
#define W_    5
#define L_    20
#define CE_   32
#define OC_   30
#define WE_   50
#define HID_  100
#define TAGS_ 36
#define TPOS  18

#define SPB   64
#define WPB   320
#define PSTR  68
#define NT    320

typedef unsigned long long ull;

__device__ float g_Pk[3 * 100 * 32];     // [k][c][oc]; k=0 has convb folded in
__device__ float g_A[5 * 100 * 104];     // [w][v][j]
__device__ float g_C[150 * 104];         // [k][j]

// ---------------- packed fp32x2 helpers ----------------
__device__ __forceinline__ ull ffma2(ull a, ull b, ull c) {
    ull d;
    asm("fma.rn.f32x2 %0, %1, %2, %3;" : "=l"(d) : "l"(a), "l"(b), "l"(c));
    return d;
}
__device__ __forceinline__ ull add2(ull a, ull b) {
    ull d;
    asm("add.rn.f32x2 %0, %1, %2;" : "=l"(d) : "l"(a), "l"(b));
    return d;
}
__device__ __forceinline__ ull pack2(float lo, float hi) {
    ull r;
    asm("mov.b64 %0, {%1, %2};"
        : "=l"(r) : "r"(__float_as_uint(lo)), "r"(__float_as_uint(hi)));
    return r;
}
__device__ __forceinline__ void unpack2(ull v, float& lo, float& hi) {
    unsigned int a, b;
    asm("mov.b64 {%0, %1}, %2;" : "=r"(a), "=r"(b) : "l"(v));
    lo = __uint_as_float(a);
    hi = __uint_as_float(b);
}
__device__ __forceinline__ float tanh_fast(float x) {
    float y;
    asm("tanh.approx.f32 %0, %1;" : "=f"(y) : "f"(x));
    return y;
}

// ---------------- Kernel 0: build P (+bias), A, C tables ----------------
__global__ void prep_kernel(const float* __restrict__ cemb,
                            const float* __restrict__ convw,
                            const float* __restrict__ convb,
                            const float* __restrict__ wemb,
                            const float* __restrict__ fc1w)
{
    const int idx = blockIdx.x * 256 + threadIdx.x;
    if (idx < 9600) {
        const int k  = idx / 3200;
        const int r  = idx - k * 3200;
        const int c  = r >> 5;
        const int oc = r & 31;
        float s = 0.f;
        if (oc < OC_) {
            const float* wr = convw + oc * (CE_ * 3) + k;
            const float* er = cemb + c * CE_;
            float p0 = 0.f, p1 = 0.f, p2 = 0.f, p3 = 0.f;
#pragma unroll
            for (int ce = 0; ce < CE_; ce += 4) {
                p0 = fmaf(wr[(ce + 0) * 3], er[ce + 0], p0);
                p1 = fmaf(wr[(ce + 1) * 3], er[ce + 1], p1);
                p2 = fmaf(wr[(ce + 2) * 3], er[ce + 2], p2);
                p3 = fmaf(wr[(ce + 3) * 3], er[ce + 3], p3);
            }
            s = (p0 + p1) + (p2 + p3);
            if (k == 0) s += convb[oc];          // fold conv bias into tap 0
        }
        g_Pk[idx] = s;
    } else if (idx < 59600) {
        const int e = idx - 9600;
        const int w = e / 10000;
        const int r = e - w * 10000;
        const int v = r / 100;
        const int j = r - v * 100;
        const float2* wr = (const float2*)(fc1w + j * 400 + w * 80);
        const float2* er = (const float2*)(wemb + v * WE_);
        float p0 = 0.f, p1 = 0.f;
#pragma unroll
        for (int d = 0; d < 25; ++d) {
            const float2 a = wr[d];
            const float2 b = er[d];
            p0 = fmaf(a.x, b.x, p0);
            p1 = fmaf(a.y, b.y, p1);
        }
        g_A[(w * 100 + v) * 104 + j] = p0 + p1;
    } else {
        const int e = idx - 59600;
        if (e >= 150 * HID_) return;
        const int j  = e / 150;
        const int kk = e - j * 150;
        const int w  = kk / OC_;
        const int oc = kk - w * OC_;
        g_C[kk * 104 + j] = fc1w[j * 400 + w * 80 + 50 + oc];
    }
}

// ---------------- Kernel 1: fully fused main ----------------
__global__ __launch_bounds__(NT, 2)
void main_kernel(const int* __restrict__ inp,
                 const float* __restrict__ fc1w, const float* __restrict__ fc1b,
                 const float* __restrict__ outw, const float* __restrict__ outb,
                 const float* __restrict__ wemb,
                 float* __restrict__ out)
{
    extern __shared__ __align__(16) float smem[];
    float* u0    = smem;                  // 9600: P, later owd (7200)
    float* poolT = smem + 9600;           // [150][68] = 10200 ; later hT[100][68]
    int*   idbuf  = (int*)(smem + 19800); // [10 warps][3][48] = 1440
    int*   wid_sh = (int*)(smem + 21240); // 320
    float* b_sh   = smem + 21560;         // 104 (fc1b)
    float* ob_sh  = smem + 21664;         // 36  (outb)

    const int tid  = threadIdx.x;
    const int warp = tid >> 5;
    const int lane = tid & 31;
    const int s0   = blockIdx.x * SPB;

    // ---- stage P (float4) + small vectors ----
    for (int i = tid; i < 2400; i += NT)
        ((float4*)u0)[i] = ((const float4*)g_Pk)[i];
    if (tid < 104) b_sh[tid] = (tid < HID_) ? fc1b[tid] : 0.f;
    if (tid < TAGS_) ob_sh[tid] = outb[tid];
    __syncthreads();

    // ---- Phase 1: pooled conv, distance-2 prefetch of input rows ----
    {
        const int half = lane >> 4;
        const int ocp  = lane & 15;
        const char* Pb = (const char*)u0 + ocp * 8;   // +0/+12800/+25600 taps
        int* bufs = idbuf + warp * 144;

        // preload iterations 0 and 1
        {
            const int* rp0 = inp + (blockIdx.x * WPB + warp * 2) * 21;
            const int* rp1 = inp + (blockIdx.x * WPB + 20 + warp * 2) * 21;
            int a0 = 0, b0 = 0, a1 = 0, b1 = 0;
            if (lane < 21) {
                a0 = rp0[lane]; b0 = rp0[21 + lane];
                a1 = rp1[lane]; b1 = rp1[21 + lane];
            }
            if (lane < 21) {
                bufs[lane] = a0 * 128;      bufs[21 + lane] = b0 * 128;
                bufs[48 + lane] = a1 * 128; bufs[69 + lane] = b1 * 128;
            }
            if (lane == 0) {
                wid_sh[warp * 2] = a0;      wid_sh[warp * 2 + 1] = b0;
                wid_sh[20 + warp * 2] = a1; wid_sh[20 + warp * 2 + 1] = b1;
            }
        }
        __syncwarp();

        for (int it = 0; it < 16; ++it) {
            const int wl = it * 20 + warp * 2;
            const int* cur = bufs + (it % 3) * 48;
            int* nxt = bufs + ((it + 2) % 3) * 48;

            int na = 0, nb = 0;
            if (it < 14) {
                const int* rp = inp + (blockIdx.x * WPB + wl + 40) * 21;
                if (lane < 21) { na = rp[lane]; nb = rp[21 + lane]; }
                if (lane == 0) { wid_sh[wl + 40] = na; wid_sh[wl + 41] = nb; }
            }

            const int* myid = cur + half * 21 + 1;
            int ca = myid[0], cb_ = myid[1];
            ull acc[TPOS];
#pragma unroll
            for (int t = 0; t < TPOS; ++t) {
                const int cc = myid[t + 2];
                const ull x0 = *(const ull*)(Pb + ca);
                const ull x1 = *(const ull*)(Pb + 12800 + cb_);
                const ull x2 = *(const ull*)(Pb + 25600 + cc);
                acc[t] = add2(add2(x0, x1), x2);
                ca = cb_; cb_ = cc;
            }

            float m0, m1;
            unpack2(acc[0], m0, m1);
#pragma unroll
            for (int t = 1; t < TPOS; ++t) {
                float x, y;
                unpack2(acc[t], x, y);
                m0 = fmaxf(m0, x);
                m1 = fmaxf(m1, y);
            }
            if (ocp < 15) {
                const int wloc = wl + half;
                const int sl   = wloc / W_;
                const int wis  = wloc - sl * W_;
                const int po   = wis * OC_ + 2 * ocp;
                poolT[po * PSTR + sl]       = m0;     // bias already in P0
                poolT[(po + 1) * PSTR + sl] = m1;
            }

            if (it < 14 && lane < 21) { nxt[lane] = na * 128; nxt[21 + lane] = nb * 128; }
            __syncwarp();
        }
    }
    __syncthreads();   // P dead; u0 free for owd

    // ---- stage owd early (LDGs overlap Phase 2/3 compute) ----
    for (int i = tid; i < TAGS_ * HID_; i += NT) {
        const int t = i / HID_;
        const int j = i - t * HID_;
        const float w = outw[i];
        u0[j * 72 + 2 * t]     = w;
        u0[j * 72 + 2 * t + 1] = w;
    }

    // ---- Phase 2: init GEMM accumulators from A table ----
    const int jg = tid >> 3;
    const int sg = tid & 7;
    const int j0 = jg * 4;
    const int sb = sg * 8;
    const bool active = (tid < 200);

    ull acc[16];
    if (active) {
        const float4 bias4 = *(const float4*)&b_sh[j0];
#pragma unroll
        for (int p = 0; p < 4; ++p) {
            const int sA = sb + 2 * p;
            float4 a4 = bias4, b4 = bias4;
#pragma unroll
            for (int w = 0; w < W_; ++w) {
                const int vA = wid_sh[sA * W_ + w];
                const int vB = wid_sh[(sA + 1) * W_ + w];
                if (vA < 100) {
                    const float4 t = *(const float4*)&g_A[(w * 100 + vA) * 104 + j0];
                    a4.x += t.x; a4.y += t.y; a4.z += t.z; a4.w += t.w;
                } else {
                    const float* er = wemb + vA * WE_;
                    for (int d = 0; d < WE_; ++d) {
                        const float e = er[d];
                        a4.x += fc1w[(j0+0)*400 + w*80 + d] * e;
                        a4.y += fc1w[(j0+1)*400 + w*80 + d] * e;
                        a4.z += fc1w[(j0+2)*400 + w*80 + d] * e;
                        a4.w += fc1w[(j0+3)*400 + w*80 + d] * e;
                    }
                }
                if (vB < 100) {
                    const float4 t = *(const float4*)&g_A[(w * 100 + vB) * 104 + j0];
                    b4.x += t.x; b4.y += t.y; b4.z += t.z; b4.w += t.w;
                } else {
                    const float* er = wemb + vB * WE_;
                    for (int d = 0; d < WE_; ++d) {
                        const float e = er[d];
                        b4.x += fc1w[(j0+0)*400 + w*80 + d] * e;
                        b4.y += fc1w[(j0+1)*400 + w*80 + d] * e;
                        b4.z += fc1w[(j0+2)*400 + w*80 + d] * e;
                        b4.w += fc1w[(j0+3)*400 + w*80 + d] * e;
                    }
                }
            }
            acc[p]      = pack2(a4.x, b4.x);
            acc[4 + p]  = pack2(a4.y, b4.y);
            acc[8 + p]  = pack2(a4.z, b4.z);
            acc[12 + p] = pack2(a4.w, b4.w);
        }
    }

    // ---- Phase 3: GEMM, C via broadcast LDG.128 from g_C ----
    if (active) {
        const float* cbase = g_C + j0;
#pragma unroll 5
        for (int kk = 0; kk < 150; ++kk) {
            const float4 wq = *(const float4*)(cbase + kk * 104);
            const float* fr = &poolT[kk * PSTR + sb];
            const ulonglong2 fA = *(const ulonglong2*)(fr);
            const ulonglong2 fB = *(const ulonglong2*)(fr + 4);
            const ull w0 = pack2(wq.x, wq.x);
            const ull w1 = pack2(wq.y, wq.y);
            const ull w2 = pack2(wq.z, wq.z);
            const ull w3 = pack2(wq.w, wq.w);
            acc[0]  = ffma2(fA.x, w0, acc[0]);
            acc[4]  = ffma2(fA.x, w1, acc[4]);
            acc[8]  = ffma2(fA.x, w2, acc[8]);
            acc[12] = ffma2(fA.x, w3, acc[12]);
            acc[1]  = ffma2(fA.y, w0, acc[1]);
            acc[5]  = ffma2(fA.y, w1, acc[5]);
            acc[9]  = ffma2(fA.y, w2, acc[9]);
            acc[13] = ffma2(fA.y, w3, acc[13]);
            acc[2]  = ffma2(fB.x, w0, acc[2]);
            acc[6]  = ffma2(fB.x, w1, acc[6]);
            acc[10] = ffma2(fB.x, w2, acc[10]);
            acc[14] = ffma2(fB.x, w3, acc[14]);
            acc[3]  = ffma2(fB.y, w0, acc[3]);
            acc[7]  = ffma2(fB.y, w1, acc[7]);
            acc[11] = ffma2(fB.y, w2, acc[11]);
            acc[15] = ffma2(fB.y, w3, acc[15]);
        }
    }
    __syncthreads();   // pool reads done before hT overlay

    // ---- tanh (MUFU) -> hT[j][s] (overlays poolT) ----
    float* hT = poolT;
    if (active) {
#pragma unroll
        for (int jj = 0; jj < 4; ++jj)
#pragma unroll
            for (int p = 0; p < 4; ++p) {
                float a, c;
                unpack2(acc[jj * 4 + p], a, c);
                *(ull*)&hT[(j0 + jj) * PSTR + sb + 2 * p] =
                    pack2(tanh_fast(a), tanh_fast(c));
            }
    }
    __syncthreads();

    // ---- Phase 4: out layer (9 of 10 warps; warp = 4 tags, lane = sample pair) ----
    if (warp < 9) {
        const int t0 = warp * 4;
        ull a4[4];
#pragma unroll
        for (int p = 0; p < 4; ++p) a4[p] = 0ull;
#pragma unroll 4
        for (int j = 0; j < HID_; ++j) {
            const ull h = *(const ull*)&hT[j * PSTR + 2 * lane];
            const float* wr = &u0[j * 72 + 2 * t0];
            const ulonglong2 w01 = *(const ulonglong2*)(wr);
            const ulonglong2 w23 = *(const ulonglong2*)(wr + 4);
            a4[0] = ffma2(h, w01.x, a4[0]);
            a4[1] = ffma2(h, w01.y, a4[1]);
            a4[2] = ffma2(h, w23.x, a4[2]);
            a4[3] = ffma2(h, w23.y, a4[3]);
        }
        float r0[4], r1[4];
#pragma unroll
        for (int tt = 0; tt < 4; ++tt) {
            float a, c;
            unpack2(a4[tt], a, c);
            const float bo = ob_sh[t0 + tt];
            r0[tt] = a + bo;
            r1[tt] = c + bo;
        }
        float* op0 = out + (s0 + 2 * lane) * TAGS_ + t0;
        *(float4*)op0           = make_float4(r0[0], r0[1], r0[2], r0[3]);
        *(float4*)(op0 + TAGS_) = make_float4(r1[0], r1[1], r1[2], r1[3]);
    }
}

// ---------------- launch ----------------
extern "C" void kernel_launch(void* const* d_in, const int* in_sizes, int n_in,
                              void* d_out, int out_size)
{
    const int*   inp   = (const int*)  d_in[0];
    const float* wemb  = (const float*)d_in[1];
    const float* cemb  = (const float*)d_in[2];
    const float* convw = (const float*)d_in[3];
    const float* convb = (const float*)d_in[4];
    const float* fc1w  = (const float*)d_in[5];
    const float* fc1b  = (const float*)d_in[6];
    const float* outw  = (const float*)d_in[7];
    const float* outb  = (const float*)d_in[8];
    float* out = (float*)d_out;

    const int smem_bytes = 21700 * 4 + 128;   // ~87 KB
    cudaFuncSetAttribute(main_kernel,
                         cudaFuncAttributeMaxDynamicSharedMemorySize, smem_bytes);

    prep_kernel<<<(9600 + 50000 + 15000 + 255) / 256, 256>>>(cemb, convw, convb,
                                                             wemb, fc1w);
    main_kernel<<<B_ / SPB, NT, smem_bytes>>>(inp, fc1w, fc1b,
                                              outw, outb, wemb, out);
}